// round 2
// baseline (speedup 1.0000x reference)
#include <cuda_runtime.h>
#include <cuda_bf16.h>

// HSMNet cost-volume + channel-sum + softmax disparity regression, fused.
// B=4, C=32, H=80, W=160, D=24. Output [B,H,W] f32.
//
// R2: channel-split parallelism. Thread = (w, cg), cg in [0,4): each thread
// accumulates 8 channels, 2-step shfl.xor butterfly completes the 32-channel
// sum, online softmax per lane (redundant), cg==0 writes.
// CTA = 640 threads per (b,h) row; 320 CTAs -> 6400 warps (vs 1600 in R1).
// smem row stride 161 so the 4 cg groups don't bank-conflict.

#define Bc 4
#define Cc 32
#define Hc 80
#define Wc 160
#define Dc 24
#define SPAD 161              // Wc + 1, odd stride -> conflict-free
#define NT 640                // 160 w * 4 cg

__global__ __launch_bounds__(NT)
void hsm_dispreg_kernel(const float* __restrict__ ref,
                        const float* __restrict__ tgt,
                        float* __restrict__ out)
{
    __shared__ float st[Cc * SPAD];   // tgt[b, c, h, :] row, padded stride

    const int h   = blockIdx.x;
    const int b   = blockIdx.y;
    const int tid = threadIdx.x;
    const int cg  = tid & 3;          // channel group 0..3
    const int w   = tid >> 2;         // 0..159

    // Stage tgt row into smem, fully coalesced: 640 threads = 4 whole
    // 160-wide rows per iteration, 8 iterations cover all 32 channels.
    {
        const int c0 = tid / Wc;            // 0..3
        const int w2 = tid - c0 * Wc;       // 0..159
#pragma unroll
        for (int i = 0; i < Cc / 4; ++i) {
            const int c = c0 + i * 4;
            st[c * SPAD + w2] = tgt[((b * Cc + c) * Hc + h) * Wc + w2];
        }
    }

    // This thread's 8 ref channels (cg*8 .. cg*8+7) at pixel (b,h,w).
    float r[8];
#pragma unroll
    for (int c8 = 0; c8 < 8; ++c8) {
        const int c = cg * 8 + c8;
        r[c8] = ref[((b * Cc + c) * Hc + h) * Wc + w];
    }
    __syncthreads();

    // Online softmax over d of v_d = sum_c |ref - tgt_shift|, with the
    // 32-channel sum assembled from 4 lanes via butterfly shuffles.
    float m = -3.0e38f;
    float s = 0.0f;
    float num = 0.0f;

#pragma unroll
    for (int d = 0; d < Dc; ++d) {
        float v = 0.0f;
        if (w >= d) {
            const float* tp = &st[cg * 8 * SPAD + (w - d)];
            float a0 = 0.f, a1 = 0.f;
#pragma unroll
            for (int c8 = 0; c8 < 8; c8 += 2) {
                a0 += fabsf(r[c8 + 0] - tp[(c8 + 0) * SPAD]);
                a1 += fabsf(r[c8 + 1] - tp[(c8 + 1) * SPAD]);
            }
            v = a0 + a1;
        }
        // lanes are (w%8)*4 + cg: xor 1 and xor 2 reduce over cg,
        // butterfly leaves the full sum in all 4 lanes.
        v += __shfl_xor_sync(0xffffffffu, v, 1);
        v += __shfl_xor_sync(0xffffffffu, v, 2);

        const float mn = fmaxf(m, v);
        const float rs = __expf(m - mn);
        const float e  = __expf(v - mn);
        s   = s   * rs + e;
        num = num * rs + (float)d * e;
        m = mn;
    }

    if (cg == 0)
        out[(b * Hc + h) * Wc + w] = num / s;
}

extern "C" void kernel_launch(void* const* d_in, const int* in_sizes, int n_in,
                              void* d_out, int out_size)
{
    const float* ref = (const float*)d_in[0];
    const float* tgt = (const float*)d_in[1];
    float* out = (float*)d_out;

    dim3 grid(Hc, Bc);   // 80 x 4 = 320 CTAs
    hsm_dispreg_kernel<<<grid, NT>>>(ref, tgt, out);
}

// round 3
// speedup vs baseline: 1.1213x; 1.1213x over previous
#include <cuda_runtime.h>
#include <cuda_bf16.h>

// HSMNet cost-volume + channel-sum + softmax disparity regression, fused.
// B=4, C=32, H=80, W=160, D=24. Output [B,H,W] f32.
//
// R3: disparity-split parallelism, zero redundant work.
// Thread = (w, dg), dg in [0,4): owns d = 6*dg .. 6*dg+5, accumulates the full
// 32-channel L1 cost for its 6 disparities into registers (two-pass softmax:
// no per-d MUFU chain). Butterfly max/sum over the 4 dg lanes at the end.
// Both ref and tgt rows staged in smem (stride 161 -> conflict-free).

#define Bc 4
#define Cc 32
#define Hc 80
#define Wc 160
#define Dc 24
#define DG 4                  // disparity groups
#define DPG 6                 // disparities per group
#define SPAD 161
#define NT (Wc * DG)          // 640 threads

__global__ __launch_bounds__(NT)
void hsm_dispreg_kernel(const float* __restrict__ ref,
                        const float* __restrict__ tgt,
                        float* __restrict__ out)
{
    __shared__ float st[Cc * SPAD];   // tgt row
    __shared__ float sr[Cc * SPAD];   // ref row

    const int h   = blockIdx.x;
    const int b   = blockIdx.y;
    const int tid = threadIdx.x;
    const int dg  = tid & (DG - 1);   // 0..3
    const int w   = tid >> 2;         // 0..159

    // Stage both rows, fully coalesced gmem reads, conflict-free smem stores.
    {
        const int c0 = tid / Wc;            // 0..3
        const int w2 = tid - c0 * Wc;       // 0..159
#pragma unroll
        for (int i = 0; i < Cc / 4; ++i) {
            const int c = c0 + i * 4;
            const int off = ((b * Cc + c) * Hc + h) * Wc + w2;
            st[c * SPAD + w2] = tgt[off];
            sr[c * SPAD + w2] = ref[off];
        }
    }
    __syncthreads();

    // Accumulate this thread's 6 disparity costs. Pure LDS+FADD stream.
    float cost[DPG] = {0.f, 0.f, 0.f, 0.f, 0.f, 0.f};
    const int d0 = dg * DPG;
    const float* tp = &st[w - d0];   // offsets c*SPAD - j are compile-time
    const float* rp = &sr[w];

#pragma unroll
    for (int c = 0; c < Cc; ++c) {
        const float rc = rp[c * SPAD];
#pragma unroll
        for (int j = 0; j < DPG; ++j) {
            if (w >= d0 + j)                    // loop-invariant predicate per j
                cost[j] += fabsf(rc - tp[c * SPAD - j]);
        }
    }

    // Two-pass softmax + expectation over all 24 disparities.
    float m = cost[0];
#pragma unroll
    for (int j = 1; j < DPG; ++j) m = fmaxf(m, cost[j]);
    m = fmaxf(m, __shfl_xor_sync(0xffffffffu, m, 1));
    m = fmaxf(m, __shfl_xor_sync(0xffffffffu, m, 2));

    float s = 0.f, num = 0.f;
#pragma unroll
    for (int j = 0; j < DPG; ++j) {
        const float e = __expf(cost[j] - m);    // invalid entries are cost=0, included
        s   += e;
        num += (float)(d0 + j) * e;
    }
    s   += __shfl_xor_sync(0xffffffffu, s, 1);
    s   += __shfl_xor_sync(0xffffffffu, s, 2);
    num += __shfl_xor_sync(0xffffffffu, num, 1);
    num += __shfl_xor_sync(0xffffffffu, num, 2);

    if (dg == 0)
        out[(b * Hc + h) * Wc + w] = num / s;
}

extern "C" void kernel_launch(void* const* d_in, const int* in_sizes, int n_in,
                              void* d_out, int out_size)
{
    const float* ref = (const float*)d_in[0];
    const float* tgt = (const float*)d_in[1];
    float* out = (float*)d_out;

    dim3 grid(Hc, Bc);   // 80 x 4 = 320 CTAs
    hsm_dispreg_kernel<<<grid, NT>>>(ref, tgt, out);
}

// round 4
// speedup vs baseline: 1.2917x; 1.1520x over previous
#include <cuda_runtime.h>
#include <cuda_bf16.h>

// HSMNet cost-volume + channel-sum + softmax disparity regression, fused.
// B=4, C=32, H=80, W=160, D=24. Output [B,H,W] f32.
//
// R4: w-register-blocking for smem reuse.
// Thread = (w-pair, dg): 2 pixels x 6 disparities = 12 accumulators.
// Per channel: 1x float2 ref + 4x float2 tgt window (5 LDS.64) feed 24 FADDs.
// Lane map wb = tid%80, dg = tid/80 -> every half-warp is dg-uniform with
// consecutive wb -> all vector LDS conflict-free. Cross-dg softmax merge via
// a small 2-sync smem reduction. 320 CTAs x 320 threads.

#define Bc 4
#define Cc 32
#define Hc 80
#define Wc 160
#define Dc 24
#define DG 4
#define DPG 6
#define WB 2
#define NWB (Wc / WB)        // 80
#define NT (NWB * DG)        // 320 threads
#define SROW 160
#define FPAD 32              // front pad so window loads below w=0 are in-bounds

__global__ __launch_bounds__(NT)
void hsm_dispreg_kernel(const float* __restrict__ ref,
                        const float* __restrict__ tgt,
                        float* __restrict__ out)
{
    __shared__ float st[FPAD + Cc * SROW];   // tgt row (front-padded)
    __shared__ float sr[FPAD + Cc * SROW];   // ref row
    __shared__ float2 redm[NT];              // per-(wb,dg) pixel maxes
    __shared__ float4 redsn[NT];             // per-(wb,dg) (s0,num0,s1,num1)

    const int h   = blockIdx.x;
    const int b   = blockIdx.y;
    const int tid = threadIdx.x;
    const int dg  = tid / NWB;               // 0..3  (half-warp uniform)
    const int wb  = tid - dg * NWB;          // 0..79
    const int w0  = wb * 2;
    const int d0  = dg * DPG;

    // Stage both rows: coalesced gmem, conflict-free smem stores.
    {
        const int ch = tid / Wc;             // 0..1
        const int w2 = tid - ch * Wc;        // 0..159
#pragma unroll
        for (int i = 0; i < Cc / 2; ++i) {
            const int c = ch + i * 2;
            const int off = ((b * Cc + c) * Hc + h) * Wc + w2;
            st[FPAD + c * SROW + w2] = tgt[off];
            sr[FPAD + c * SROW + w2] = ref[off];
        }
    }
    __syncthreads();

    // 12 accumulators: cost[pixel][j], d = d0 + j.
    float cost0[DPG] = {0.f, 0.f, 0.f, 0.f, 0.f, 0.f};
    float cost1[DPG] = {0.f, 0.f, 0.f, 0.f, 0.f, 0.f};

    const float* rp = &sr[FPAD + w0];
    const float* tp = &st[FPAD + w0 - d0 - 6];   // window base (even -> 8B aligned)

#pragma unroll 4
    for (int c = 0; c < Cc; ++c) {
        const float2 r = *(const float2*)(rp + c * SROW);
        float t[8];
#pragma unroll
        for (int k = 0; k < 4; ++k) {
            const float2 tt = *(const float2*)(tp + c * SROW + 2 * k);
            t[2 * k]     = tt.x;
            t[2 * k + 1] = tt.y;
        }
        // tgt logical index w0+p-d0-j == window slot (6-j+p)
#pragma unroll
        for (int j = 0; j < DPG; ++j) {
            if (w0 >= d0 + j)     cost0[j] += fabsf(r.x - t[6 - j]);
            if (w0 + 1 >= d0 + j) cost1[j] += fabsf(r.y - t[7 - j]);
        }
    }

    // ---- softmax + expectation over all 24 disparities (exact two-pass) ----
    // Local max per pixel.
    float m0 = cost0[0], m1 = cost1[0];
#pragma unroll
    for (int j = 1; j < DPG; ++j) {
        m0 = fmaxf(m0, cost0[j]);
        m1 = fmaxf(m1, cost1[j]);
    }
    redm[dg * NWB + wb] = make_float2(m0, m1);
    __syncthreads();

    const float2 ma = redm[0 * NWB + wb];
    const float2 mb = redm[1 * NWB + wb];
    const float2 mc = redm[2 * NWB + wb];
    const float2 md = redm[3 * NWB + wb];
    const float M0 = fmaxf(fmaxf(ma.x, mb.x), fmaxf(mc.x, md.x));
    const float M1 = fmaxf(fmaxf(ma.y, mb.y), fmaxf(mc.y, md.y));

    float s0 = 0.f, n0 = 0.f, s1 = 0.f, n1 = 0.f;
#pragma unroll
    for (int j = 0; j < DPG; ++j) {
        const float e0 = __expf(cost0[j] - M0);   // invalid entries are cost 0
        const float e1 = __expf(cost1[j] - M1);
        s0 += e0;  n0 += (float)(d0 + j) * e0;
        s1 += e1;  n1 += (float)(d0 + j) * e1;
    }
    redsn[dg * NWB + wb] = make_float4(s0, n0, s1, n1);
    __syncthreads();

    if (dg == 0) {
        const float4 x0 = redsn[0 * NWB + wb];
        const float4 x1 = redsn[1 * NWB + wb];
        const float4 x2 = redsn[2 * NWB + wb];
        const float4 x3 = redsn[3 * NWB + wb];
        const float S0 = (x0.x + x1.x) + (x2.x + x3.x);
        const float N0 = (x0.y + x1.y) + (x2.y + x3.y);
        const float S1 = (x0.z + x1.z) + (x2.z + x3.z);
        const float N1 = (x0.w + x1.w) + (x2.w + x3.w);
        float2 o;
        o.x = N0 / S0;
        o.y = N1 / S1;
        *(float2*)&out[(b * Hc + h) * Wc + w0] = o;
    }
}

extern "C" void kernel_launch(void* const* d_in, const int* in_sizes, int n_in,
                              void* d_out, int out_size)
{
    const float* ref = (const float*)d_in[0];
    const float* tgt = (const float*)d_in[1];
    float* out = (float*)d_out;

    dim3 grid(Hc, Bc);   // 80 x 4 = 320 CTAs
    hsm_dispreg_kernel<<<grid, NT>>>(ref, tgt, out);
}

// round 5
// speedup vs baseline: 1.2948x; 1.0025x over previous
#include <cuda_runtime.h>
#include <cuda_bf16.h>

// HSMNet cost-volume + channel-sum + softmax disparity regression, fused.
// B=4, C=32, H=80, W=160, D=24. Output [B,H,W] f32.
//
// R5: half-row CTAs (640 CTAs x 160 thr) for balance + occupancy;
// dg-in-warp lane map (dg = tid&3) -> conflict-free LDS.64 and shfl-based
// softmax merge (single __syncthreads in the whole kernel).
// Thread = (w-pair, dg): 2 pixels x 6 disparities, 5 LDS.64 -> 24 FADD / channel.

#define Bc 4
#define Cc 32
#define Hc 80
#define Wc 160
#define Dc 24
#define DG 4
#define DPG 6
#define HALF 80              // pixels per CTA
#define NWB (HALF / 2)       // 40 w-pairs
#define NT (NWB * DG)        // 160 threads
#define TROW 112             // tgt cols staged: [w_start-32, w_start+80)
#define RROW 80              // ref cols staged: [w_start, w_start+80)

__global__ __launch_bounds__(NT)
void hsm_dispreg_kernel(const float* __restrict__ ref,
                        const float* __restrict__ tgt,
                        float* __restrict__ out)
{
    __shared__ float st[Cc * TROW];   // tgt window (front 32 cols may be unused/uninit)
    __shared__ float sr[Cc * RROW];   // ref half-row

    const int half = blockIdx.x;             // 0,1
    const int h    = blockIdx.y;
    const int b    = blockIdx.z;
    const int tid  = threadIdx.x;
    const int dg   = tid & 3;                // 0..3, fast within warp
    const int wb   = tid >> 2;               // 0..39
    const int w_start = half * HALF;
    const int w0   = w_start + wb * 2;
    const int d0   = dg * DPG;

    // ---- stage tgt window [w_start-32, w_start+80) x 32 channels ----
    {
        const int rowbase = (b * Cc * Hc + h) * Wc;  // + c*Hc*Wc handled below
#pragma unroll
        for (int k = 0; k < (Cc * TROW + NT - 1) / NT; ++k) {
            const int idx = tid + k * NT;
            if (idx < Cc * TROW) {
                const int c = idx / TROW;
                const int l = idx - c * TROW;
                const int gcol = w_start - 32 + l;
                if ((unsigned)gcol < (unsigned)Wc)
                    st[idx] = tgt[rowbase + c * Hc * Wc + gcol];
            }
        }
        // ---- stage ref half-row [w_start, w_start+80) ----
#pragma unroll
        for (int k = 0; k < (Cc * RROW) / NT; ++k) {
            const int idx = tid + k * NT;
            const int c = idx / RROW;
            const int l = idx - c * RROW;
            sr[idx] = ref[rowbase + c * Hc * Wc + w_start + l];
        }
    }
    __syncthreads();

    // ---- accumulate 2 pixels x 6 disparities ----
    float cost0[DPG] = {0.f, 0.f, 0.f, 0.f, 0.f, 0.f};
    float cost1[DPG] = {0.f, 0.f, 0.f, 0.f, 0.f, 0.f};

    const float* rp = &sr[wb * 2];                       // + c*RROW
    const float* tp = &st[wb * 2 + 26 - d0];             // window base, even -> 8B aligned

#pragma unroll 4
    for (int c = 0; c < Cc; ++c) {
        const float2 r = *(const float2*)(rp + c * RROW);
        float t[8];
#pragma unroll
        for (int k = 0; k < 4; ++k) {
            const float2 tt = *(const float2*)(tp + c * TROW + 2 * k);
            t[2 * k]     = tt.x;
            t[2 * k + 1] = tt.y;
        }
        // t[6-j] = tgt[w0 - (d0+j)],  t[7-j] = tgt[w0+1 - (d0+j)]
#pragma unroll
        for (int j = 0; j < DPG; ++j) {
            if (w0 >= d0 + j)     cost0[j] += fabsf(r.x - t[6 - j]);
            if (w0 + 1 >= d0 + j) cost1[j] += fabsf(r.y - t[7 - j]);
        }
    }

    // ---- exact two-pass softmax + expectation, merged across dg via shfl ----
    float m0 = cost0[0], m1 = cost1[0];
#pragma unroll
    for (int j = 1; j < DPG; ++j) {
        m0 = fmaxf(m0, cost0[j]);
        m1 = fmaxf(m1, cost1[j]);
    }
    m0 = fmaxf(m0, __shfl_xor_sync(0xffffffffu, m0, 1));
    m0 = fmaxf(m0, __shfl_xor_sync(0xffffffffu, m0, 2));
    m1 = fmaxf(m1, __shfl_xor_sync(0xffffffffu, m1, 1));
    m1 = fmaxf(m1, __shfl_xor_sync(0xffffffffu, m1, 2));

    float s0 = 0.f, n0 = 0.f, s1 = 0.f, n1 = 0.f;
#pragma unroll
    for (int j = 0; j < DPG; ++j) {
        const float e0 = __expf(cost0[j] - m0);   // invalid entries carry cost 0 (as reference)
        const float e1 = __expf(cost1[j] - m1);
        s0 += e0;  n0 += (float)(d0 + j) * e0;
        s1 += e1;  n1 += (float)(d0 + j) * e1;
    }
    s0 += __shfl_xor_sync(0xffffffffu, s0, 1);
    s0 += __shfl_xor_sync(0xffffffffu, s0, 2);
    n0 += __shfl_xor_sync(0xffffffffu, n0, 1);
    n0 += __shfl_xor_sync(0xffffffffu, n0, 2);
    s1 += __shfl_xor_sync(0xffffffffu, s1, 1);
    s1 += __shfl_xor_sync(0xffffffffu, s1, 2);
    n1 += __shfl_xor_sync(0xffffffffu, n1, 1);
    n1 += __shfl_xor_sync(0xffffffffu, n1, 2);

    if (dg == 0) {
        float2 o;
        o.x = n0 / s0;
        o.y = n1 / s1;
        *(float2*)&out[(b * Hc + h) * Wc + w0] = o;
    }
}

extern "C" void kernel_launch(void* const* d_in, const int* in_sizes, int n_in,
                              void* d_out, int out_size)
{
    const float* ref = (const float*)d_in[0];
    const float* tgt = (const float*)d_in[1];
    float* out = (float*)d_out;

    dim3 grid(2, Hc, Bc);   // 640 CTAs
    hsm_dispreg_kernel<<<grid, NT>>>(ref, tgt, out);
}